// round 5
// baseline (speedup 1.0000x reference)
#include <cuda_runtime.h>
#include <cstdint>

#define N_SRC0 286000
#define N_DST0 11000
#define N_E0   275000
#define N_DST1 1000
#define N_E1   10000
#define F_IN   602
#define F_HID  256
#define F_OUT  41

// ---------------- scratch (static device globals; no allocation) -------------
__device__ float g_agg0[(size_t)N_DST0 * F_IN + 8];
__device__ float g_h   [(size_t)N_DST0 * F_HID];
__device__ float g_agg1[(size_t)N_DST1 * F_HID];
__device__ float g_cnt1[N_DST1];
// CSR build for layer-0 edges
__device__ int   g_deg0[N_DST0];
__device__ int   g_cur0[N_DST0];
__device__ int   g_off0[N_DST0 + 1];
__device__ int   g_eidx[N_E0];

// ---------------- zero small scratch ------------------------------------------
__global__ void k_zero() {
    int i  = blockIdx.x * blockDim.x + threadIdx.x;
    int st = gridDim.x * blockDim.x;
    for (int j = i; j < N_DST0; j += st) { g_deg0[j] = 0; g_cur0[j] = 0; }
    for (int j = i; j < N_DST1 * F_HID; j += st) g_agg1[j] = 0.f;
    for (int j = i; j < N_DST1; j += st) g_cnt1[j] = 0.f;
}

// ---------------- CSR build ----------------------------------------------------
__global__ void k_hist(const int* __restrict__ dst) {
    int i = blockIdx.x * blockDim.x + threadIdx.x;
    if (i < N_E0) atomicAdd(&g_deg0[dst[i]], 1);
}

__global__ void __launch_bounds__(1024)
k_prefix() {
    __shared__ int sh[1024];
    __shared__ int carry;
    int t = threadIdx.x;
    if (t == 0) carry = 0;
    __syncthreads();
    for (int base = 0; base < N_DST0; base += 1024) {
        int v = (base + t < N_DST0) ? g_deg0[base + t] : 0;
        sh[t] = v;
        __syncthreads();
        #pragma unroll
        for (int ofs = 1; ofs < 1024; ofs <<= 1) {
            int add = (t >= ofs) ? sh[t - ofs] : 0;
            __syncthreads();
            sh[t] += add;
            __syncthreads();
        }
        if (base + t < N_DST0) g_off0[base + t] = carry + sh[t] - v;
        int tot = sh[1023];
        __syncthreads();
        if (t == 0) carry += tot;
        __syncthreads();
    }
    if (t == 0) g_off0[N_DST0] = carry;
}

__global__ void k_fill(const int* __restrict__ src, const int* __restrict__ dst) {
    int i = blockIdx.x * blockDim.x + threadIdx.x;
    if (i < N_E0) {
        int d = dst[i];
        int p = atomicAdd(&g_cur0[d], 1);
        g_eidx[g_off0[d] + p] = src[i];
    }
}

// ---------------- layer-0 mean aggregation: pull (one block per dst) ----------
__global__ void __launch_bounds__(256)
k_agg0(const float* __restrict__ x) {
    int d = blockIdx.x;
    int t = threadIdx.x;
    int beg = g_off0[d], end = g_off0[d + 1];
    int deg = end - beg;

    int f0 = t, f1 = t + 256, f2 = t + 512;
    bool has2 = (f2 < F_IN);          // t < 90
    float a0 = 0.f, a1 = 0.f, a2 = 0.f;

    int e = beg;
    for (; e + 1 < end; e += 2) {
        int s0 = __ldg(&g_eidx[e]);
        int s1 = __ldg(&g_eidx[e + 1]);
        const float* r0 = x + (size_t)s0 * F_IN;
        const float* r1 = x + (size_t)s1 * F_IN;
        float u0 = __ldg(r0 + f0), v0 = __ldg(r1 + f0);
        float u1 = __ldg(r0 + f1), v1 = __ldg(r1 + f1);
        float u2 = 0.f, v2 = 0.f;
        if (has2) { u2 = __ldg(r0 + f2); v2 = __ldg(r1 + f2); }
        a0 += u0 + v0; a1 += u1 + v1; a2 += u2 + v2;
    }
    if (e < end) {
        int s0 = __ldg(&g_eidx[e]);
        const float* r0 = x + (size_t)s0 * F_IN;
        a0 += __ldg(r0 + f0);
        a1 += __ldg(r0 + f1);
        if (has2) a2 += __ldg(r0 + f2);
    }

    float inv = (deg > 0) ? (1.f / (float)deg) : 0.f;
    float* o = g_agg0 + (size_t)d * F_IN;
    o[f0] = a0 * inv;
    o[f1] = a1 * inv;
    if (has2) o[f2] = a2 * inv;
}

// =============================================================================
// layer-0 GEMM via tf32 mma.sync  (M=11000, N=256, K=2x602)
// h = relu([x[:N_DST0] | agg0] @ [Wself0; Wneigh0] + b0)
// =============================================================================

__device__ __forceinline__ uint32_t f2tf(float f) {
    uint32_t r; asm("cvt.rna.tf32.f32 %0, %1;" : "=r"(r) : "f"(f)); return r;
}

#define MMA_TF32(c, a, br0, br1)                                          \
    asm volatile("mma.sync.aligned.m16n8k8.row.col.f32.tf32.tf32.f32 "   \
        "{%0,%1,%2,%3}, {%4,%5,%6,%7}, {%8,%9}, {%0,%1,%2,%3};"          \
        : "+f"(c[0]), "+f"(c[1]), "+f"(c[2]), "+f"(c[3])                  \
        : "r"(a[0]), "r"(a[1]), "r"(a[2]), "r"(a[3]), "r"(br0), "r"(br1))

struct AStage { float v[4][4]; };

__device__ __forceinline__ void lda(AStage& s, const float* __restrict__ base,
                                    int rowBase, int lm, int kq, int k0) {
    #pragma unroll
    for (int p = 0; p < 4; p++) {
        int gm = rowBase + p * 32 + lm;
        int gk = k0 + kq * 4;
        float2 v0 = make_float2(0.f, 0.f), v1 = make_float2(0.f, 0.f);
        if (gm < N_DST0) {
            const float* rp = base + (size_t)gm * F_IN;
            if (gk < F_IN)     v0 = __ldg((const float2*)(rp + gk));
            if (gk + 2 < F_IN) v1 = __ldg((const float2*)(rp + gk + 2));
        }
        s.v[p][0] = v0.x; s.v[p][1] = v0.y;
        s.v[p][2] = v1.x; s.v[p][3] = v1.y;
    }
}

__device__ __forceinline__ void sta(uint32_t (*As)[2][4][32], const AStage& s,
                                    int lm, int kq) {
    int k8 = kq >> 1;
    #pragma unroll
    for (int p = 0; p < 4; p++) {
        int m   = p * 32 + lm;
        int mt  = m >> 4;
        int reg = ((m >> 3) & 1) + ((kq & 1) << 1);
        int lb  = (m & 7) * 4;
        uint4 w;
        w.x = f2tf(s.v[p][0]); w.y = f2tf(s.v[p][1]);
        w.z = f2tf(s.v[p][2]); w.w = f2tf(s.v[p][3]);
        *(uint4*)&As[mt][k8][reg][lb] = w;
    }
}

__device__ __forceinline__ void ldb(uint32_t* b, const float* __restrict__ W,
                                    int k0, int cb, int tig, int gid) {
    #pragma unroll
    for (int k8 = 0; k8 < 2; k8++)
        #pragma unroll
        for (int nt = 0; nt < 4; nt++)
            #pragma unroll
            for (int r = 0; r < 2; r++) {
                int k = k0 + k8 * 8 + r * 4 + tig;
                int c = cb + nt * 8 + gid;
                float v = (k < F_IN) ? __ldg(&W[(size_t)k * F_HID + c]) : 0.f;
                b[(k8 * 4 + nt) * 2 + r] = f2tf(v);
            }
}

__device__ __forceinline__ void compute_tile(const uint32_t (*As)[2][4][32],
                                             const uint32_t* b,
                                             float acc[4][4][4],
                                             int wm, int lane) {
    #pragma unroll
    for (int k8 = 0; k8 < 2; k8++) {
        uint32_t a[4][4];
        #pragma unroll
        for (int mt = 0; mt < 4; mt++)
            #pragma unroll
            for (int r = 0; r < 4; r++)
                a[mt][r] = As[wm * 4 + mt][k8][r][lane];
        #pragma unroll
        for (int mt = 0; mt < 4; mt++)
            #pragma unroll
            for (int nt = 0; nt < 4; nt++)
                MMA_TF32(acc[mt][nt], a[mt],
                         b[(k8 * 4 + nt) * 2], b[(k8 * 4 + nt) * 2 + 1]);
    }
}

__global__ void __launch_bounds__(128, 3)
k_gemm0(const float* __restrict__ x,
        const float* __restrict__ Wself,
        const float* __restrict__ Wneigh,
        const float* __restrict__ b0) {
    __shared__ __align__(16) uint32_t As[2][8][2][4][32];  // 16 KB

    const int t    = threadIdx.x;
    const int warp = t >> 5, lane = t & 31;
    const int wm = warp & 1, wn = warp >> 1;
    const int gid = lane >> 2, tig = lane & 3;
    const int rowBase = blockIdx.y * 128;
    const int colBase = blockIdx.x * 64;
    const int lm = t >> 2;
    const int kq = t & 3;

    float acc[4][4][4];
    #pragma unroll
    for (int i = 0; i < 4; i++)
        #pragma unroll
        for (int j = 0; j < 4; j++)
            #pragma unroll
            for (int r = 0; r < 4; r++) acc[i][j][r] = 0.f;

    const int HT = 38;
    const int TILES = 2 * HT;
    const int cb = colBase + wn * 32;

    AStage st;
    uint32_t bC[16], bN[16];

    lda(st, x, rowBase, lm, kq, 0);
    ldb(bC, Wself, 0, cb, tig, gid);
    sta(As[0], st, lm, kq);
    __syncthreads();

    int buf = 0;
    for (int tile = 0; tile < TILES; tile++) {
        bool more = (tile + 1 < TILES);
        if (more) {
            int nt  = tile + 1;
            int h   = (nt >= HT);
            int k0  = (nt - (h ? HT : 0)) * 16;
            lda(st, h ? g_agg0 : x, rowBase, lm, kq, k0);
            ldb(bN, h ? Wneigh : Wself, k0, cb, tig, gid);
        }
        compute_tile(As[buf], bC, acc, wm, lane);
        if (more) {
            sta(As[buf ^ 1], st, lm, kq);
            __syncthreads();
            buf ^= 1;
            #pragma unroll
            for (int i = 0; i < 16; i++) bC[i] = bN[i];
        }
    }

    #pragma unroll
    for (int mt = 0; mt < 4; mt++) {
        int r0 = rowBase + wm * 64 + mt * 16 + gid;
        int r1 = r0 + 8;
        #pragma unroll
        for (int nt = 0; nt < 4; nt++) {
            int c = cb + nt * 8 + tig * 2;
            float bb0 = __ldg(&b0[c]);
            float bb1 = __ldg(&b0[c + 1]);
            if (r0 < N_DST0) {
                float2 v = make_float2(fmaxf(acc[mt][nt][0] + bb0, 0.f),
                                       fmaxf(acc[mt][nt][1] + bb1, 0.f));
                *(float2*)&g_h[(size_t)r0 * F_HID + c] = v;
            }
            if (r1 < N_DST0) {
                float2 v = make_float2(fmaxf(acc[mt][nt][2] + bb0, 0.f),
                                       fmaxf(acc[mt][nt][3] + bb1, 0.f));
                *(float2*)&g_h[(size_t)r1 * F_HID + c] = v;
            }
        }
    }
}

// ---------------- layer-1 scatter: one warp per edge ---------------------------
__global__ void k_scatter1(const int* __restrict__ src,
                           const int* __restrict__ dst) {
    int gthread = blockIdx.x * blockDim.x + threadIdx.x;
    int warp = gthread >> 5;
    int lane = threadIdx.x & 31;
    if (warp >= N_E1) return;
    int s = src[warp];
    int d = dst[warp];
    const float2* hs = (const float2*)(g_h + (size_t)s * F_HID);
    float*        ag = g_agg1 + (size_t)d * F_HID;
    #pragma unroll
    for (int f = lane; f < F_HID / 2; f += 32) {
        float2 v = hs[f];
        atomicAdd(ag + 2*f,     v.x);
        atomicAdd(ag + 2*f + 1, v.y);
    }
    if (lane == 0) atomicAdd(&g_cnt1[d], 1.f);
}

// ---------------- output GEMM: one block per row (mean folded in) -------------
__global__ void __launch_bounds__(64)
k_out(const float* __restrict__ Ws1,
      const float* __restrict__ Wn1,
      const float* __restrict__ b1,
      float* __restrict__ out) {
    __shared__ float hs[F_HID];
    __shared__ float as[F_HID];
    int row = blockIdx.x;
    int t = threadIdx.x;
    float inv = 1.f / fmaxf(g_cnt1[row], 1.f);
    float4 hv = ((const float4*)(g_h    + (size_t)row * F_HID))[t];
    float4 av = ((const float4*)(g_agg1 + (size_t)row * F_HID))[t];
    av.x *= inv; av.y *= inv; av.z *= inv; av.w *= inv;
    ((float4*)hs)[t] = hv;
    ((float4*)as)[t] = av;
    __syncthreads();
    if (t < F_OUT) {
        float acc = __ldg(&b1[t]);
        #pragma unroll 8
        for (int k = 0; k < F_HID; k++) {
            acc += hs[k] * __ldg(&Ws1[k * F_OUT + t]);
            acc += as[k] * __ldg(&Wn1[k * F_OUT + t]);
        }
        out[row * F_OUT + t] = acc;
    }
}

// ---------------- launch ------------------------------------------------------
extern "C" void kernel_launch(void* const* d_in, const int* in_sizes, int n_in,
                              void* d_out, int out_size) {
    const float* x      = (const float*)d_in[0];
    const float* Wself0 = (const float*)d_in[1];
    const float* Wneigh0= (const float*)d_in[2];
    const float* b0     = (const float*)d_in[3];
    const float* Wself1 = (const float*)d_in[4];
    const float* Wneigh1= (const float*)d_in[5];
    const float* b1     = (const float*)d_in[6];
    const int*   e0_src = (const int*)d_in[7];
    const int*   e0_dst = (const int*)d_in[8];
    const int*   e1_src = (const int*)d_in[9];
    const int*   e1_dst = (const int*)d_in[10];
    float* out = (float*)d_out;

    k_zero<<<256, 256>>>();
    k_hist<<<(N_E0 + 255) / 256, 256>>>(e0_dst);
    k_prefix<<<1, 1024>>>();
    k_fill<<<(N_E0 + 255) / 256, 256>>>(e0_src, e0_dst);
    k_agg0<<<N_DST0, 256>>>(x);

    {
        dim3 grid(F_HID / 64, (N_DST0 + 127) / 128);   // (4, 86)
        k_gemm0<<<grid, 128>>>(x, Wself0, Wneigh0, b0);
    }

    {
        int blocks = (N_E1 * 32 + 255) / 256;
        k_scatter1<<<blocks, 256>>>(e1_src, e1_dst);
    }

    k_out<<<N_DST1, 64>>>(Wself1, Wneigh1, b1, out);
}

// round 14
// speedup vs baseline: 1.0336x; 1.0336x over previous
#include <cuda_runtime.h>
#include <cstdint>

#define N_SRC0 286000
#define N_DST0 11000
#define N_E0   275000
#define N_DST1 1000
#define N_E1   10000
#define F_IN   602
#define F_HID  256
#define F_OUT  41

// ---------------- scratch (static device globals; no allocation) -------------
__device__ float g_agg0[(size_t)N_DST0 * F_IN + 8];
__device__ float g_h   [(size_t)N_DST0 * F_HID];
__device__ float g_agg1[(size_t)N_DST1 * F_HID];
__device__ float g_cnt1[N_DST1];
__device__ int   g_deg0[N_DST0];
__device__ int   g_cur0[N_DST0];
__device__ int   g_off0[N_DST0 + 1];
__device__ int   g_eidx[N_E0];

// ---------------- zero small scratch ------------------------------------------
__global__ void k_zero() {
    int i  = blockIdx.x * blockDim.x + threadIdx.x;
    int st = gridDim.x * blockDim.x;
    for (int j = i; j < N_DST0; j += st) { g_deg0[j] = 0; g_cur0[j] = 0; }
    for (int j = i; j < N_DST1 * F_HID; j += st) g_agg1[j] = 0.f;
    for (int j = i; j < N_DST1; j += st) g_cnt1[j] = 0.f;
}

// ---------------- CSR build ----------------------------------------------------
__global__ void k_hist(const int* __restrict__ dst) {
    int i = blockIdx.x * blockDim.x + threadIdx.x;
    if (i < N_E0) atomicAdd(&g_deg0[dst[i]], 1);
}

__global__ void __launch_bounds__(1024)
k_prefix() {
    __shared__ int warp_sums[32];
    __shared__ int carry_s;
    int t = threadIdx.x, lane = t & 31, w = t >> 5;
    if (t == 0) carry_s = 0;
    __syncthreads();
    for (int base = 0; base < N_DST0; base += 1024) {
        int v = (base + t < N_DST0) ? g_deg0[base + t] : 0;
        int s = v;
        #pragma unroll
        for (int o = 1; o < 32; o <<= 1) {
            int y = __shfl_up_sync(0xffffffffu, s, o);
            if (lane >= o) s += y;
        }
        if (lane == 31) warp_sums[w] = s;
        __syncthreads();
        if (w == 0) {
            int ws = warp_sums[lane];
            #pragma unroll
            for (int o = 1; o < 32; o <<= 1) {
                int y = __shfl_up_sync(0xffffffffu, ws, o);
                if (lane >= o) ws += y;
            }
            warp_sums[lane] = ws;
        }
        __syncthreads();
        int excl = (w ? warp_sums[w - 1] : 0) + s - v + carry_s;
        if (base + t < N_DST0) g_off0[base + t] = excl;
        int tot = warp_sums[31];
        __syncthreads();
        if (t == 0) carry_s += tot;
        __syncthreads();
    }
    if (t == 0) g_off0[N_DST0] = carry_s;
}

__global__ void k_fill(const int* __restrict__ src, const int* __restrict__ dst) {
    int i = blockIdx.x * blockDim.x + threadIdx.x;
    if (i < N_E0) {
        int d = dst[i];
        int p = atomicAdd(&g_cur0[d], 1);
        g_eidx[g_off0[d] + p] = src[i];
    }
}

// ---------------- layer-0 mean aggregation: pull (one block per dst) ----------
__global__ void __launch_bounds__(256)
k_agg0(const float* __restrict__ x) {
    int d = blockIdx.x;
    int t = threadIdx.x;
    int beg = g_off0[d], end = g_off0[d + 1];
    int deg = end - beg;

    int f0 = t, f1 = t + 256, f2 = t + 512;
    bool has2 = (f2 < F_IN);
    float a0 = 0.f, a1 = 0.f, a2 = 0.f;

    int e = beg;
    for (; e + 3 < end; e += 4) {
        int s0 = __ldg(&g_eidx[e]);
        int s1 = __ldg(&g_eidx[e + 1]);
        int s2 = __ldg(&g_eidx[e + 2]);
        int s3 = __ldg(&g_eidx[e + 3]);
        const float* r0 = x + (size_t)s0 * F_IN;
        const float* r1 = x + (size_t)s1 * F_IN;
        const float* r2 = x + (size_t)s2 * F_IN;
        const float* r3 = x + (size_t)s3 * F_IN;
        float u00 = __ldg(r0 + f0), u10 = __ldg(r1 + f0),
              u20 = __ldg(r2 + f0), u30 = __ldg(r3 + f0);
        float u01 = __ldg(r0 + f1), u11 = __ldg(r1 + f1),
              u21 = __ldg(r2 + f1), u31 = __ldg(r3 + f1);
        float u02 = 0.f, u12 = 0.f, u22 = 0.f, u32 = 0.f;
        if (has2) { u02 = __ldg(r0 + f2); u12 = __ldg(r1 + f2);
                    u22 = __ldg(r2 + f2); u32 = __ldg(r3 + f2); }
        a0 += (u00 + u10) + (u20 + u30);
        a1 += (u01 + u11) + (u21 + u31);
        a2 += (u02 + u12) + (u22 + u32);
    }
    for (; e < end; e++) {
        int s0 = __ldg(&g_eidx[e]);
        const float* r0 = x + (size_t)s0 * F_IN;
        a0 += __ldg(r0 + f0);
        a1 += __ldg(r0 + f1);
        if (has2) a2 += __ldg(r0 + f2);
    }

    float inv = (deg > 0) ? (1.f / (float)deg) : 0.f;
    float* o = g_agg0 + (size_t)d * F_IN;
    o[f0] = a0 * inv;
    o[f1] = a1 * inv;
    if (has2) o[f2] = a2 * inv;
}

// =============================================================================
// layer-0 GEMM via tf32 mma.sync, split into two phases:
//   phase 0: g_h = x[:N_DST0] @ Wself0 + b0            (runs on side stream)
//   phase 1: g_h = relu(g_h + g_agg0 @ Wneigh0)        (after join)
// NOTE: phase 1 resolves g_agg0 INSIDE the kernel (device symbol); passing it
// from host code was the round-5 bug (invalid host-side symbol address).
// =============================================================================

__device__ __forceinline__ uint32_t f2tf(float f) {
    uint32_t r; asm("cvt.rna.tf32.f32 %0, %1;" : "=r"(r) : "f"(f)); return r;
}

#define MMA_TF32(c, a, br0, br1)                                          \
    asm volatile("mma.sync.aligned.m16n8k8.row.col.f32.tf32.tf32.f32 "   \
        "{%0,%1,%2,%3}, {%4,%5,%6,%7}, {%8,%9}, {%0,%1,%2,%3};"          \
        : "+f"(c[0]), "+f"(c[1]), "+f"(c[2]), "+f"(c[3])                  \
        : "r"(a[0]), "r"(a[1]), "r"(a[2]), "r"(a[3]), "r"(br0), "r"(br1))

struct AStage { float v[4][4]; };

__device__ __forceinline__ void lda(AStage& s, const float* __restrict__ base,
                                    int rowBase, int lm, int kq, int k0) {
    #pragma unroll
    for (int p = 0; p < 4; p++) {
        int gm = rowBase + p * 32 + lm;
        int gk = k0 + kq * 4;
        float2 v0 = make_float2(0.f, 0.f), v1 = make_float2(0.f, 0.f);
        if (gm < N_DST0) {
            const float* rp = base + (size_t)gm * F_IN;
            if (gk < F_IN)     v0 = __ldg((const float2*)(rp + gk));
            if (gk + 2 < F_IN) v1 = __ldg((const float2*)(rp + gk + 2));
        }
        s.v[p][0] = v0.x; s.v[p][1] = v0.y;
        s.v[p][2] = v1.x; s.v[p][3] = v1.y;
    }
}

__device__ __forceinline__ void sta(uint32_t (*As)[2][4][32], const AStage& s,
                                    int lm, int kq) {
    int k8 = kq >> 1;
    #pragma unroll
    for (int p = 0; p < 4; p++) {
        int m   = p * 32 + lm;
        int mt  = m >> 4;
        int reg = ((m >> 3) & 1) + ((kq & 1) << 1);
        int lb  = (m & 7) * 4;
        uint4 w;
        w.x = f2tf(s.v[p][0]); w.y = f2tf(s.v[p][1]);
        w.z = f2tf(s.v[p][2]); w.w = f2tf(s.v[p][3]);
        *(uint4*)&As[mt][k8][reg][lb] = w;
    }
}

__device__ __forceinline__ void ldb(uint32_t* b, const float* __restrict__ W,
                                    int k0, int cb, int tig, int gid) {
    #pragma unroll
    for (int k8 = 0; k8 < 2; k8++)
        #pragma unroll
        for (int nt = 0; nt < 4; nt++)
            #pragma unroll
            for (int r = 0; r < 2; r++) {
                int k = k0 + k8 * 8 + r * 4 + tig;
                int c = cb + nt * 8 + gid;
                float v = (k < F_IN) ? __ldg(&W[(size_t)k * F_HID + c]) : 0.f;
                b[(k8 * 4 + nt) * 2 + r] = f2tf(v);
            }
}

__device__ __forceinline__ void compute_tile(const uint32_t (*As)[2][4][32],
                                             const uint32_t* b,
                                             float acc[4][4][4],
                                             int wm, int lane) {
    #pragma unroll
    for (int k8 = 0; k8 < 2; k8++) {
        uint32_t a[4][4];
        #pragma unroll
        for (int mt = 0; mt < 4; mt++)
            #pragma unroll
            for (int r = 0; r < 4; r++)
                a[mt][r] = As[wm * 4 + mt][k8][r][lane];
        #pragma unroll
        for (int mt = 0; mt < 4; mt++)
            #pragma unroll
            for (int nt = 0; nt < 4; nt++)
                MMA_TF32(acc[mt][nt], a[mt],
                         b[(k8 * 4 + nt) * 2], b[(k8 * 4 + nt) * 2 + 1]);
    }
}

template <int PHASE>
__global__ void __launch_bounds__(128, 3)
k_gemm(const float* __restrict__ A,
       const float* __restrict__ W,
       const float* __restrict__ b0) {
    __shared__ __align__(16) uint32_t As[2][8][2][4][32];  // 16 KB

    const int t    = threadIdx.x;
    const int warp = t >> 5, lane = t & 31;
    const int wm = warp & 1, wn = warp >> 1;
    const int gid = lane >> 2, tig = lane & 3;
    const int rowBase = blockIdx.y * 128;
    const int colBase = blockIdx.x * 64;
    const int lm = t >> 2;
    const int kq = t & 3;

    // device-side resolution of the A matrix (FIX: never pass g_agg0 from host)
    const float* Abase = (PHASE == 0) ? A : (const float*)g_agg0;

    float acc[4][4][4];
    #pragma unroll
    for (int i = 0; i < 4; i++)
        #pragma unroll
        for (int j = 0; j < 4; j++)
            #pragma unroll
            for (int r = 0; r < 4; r++) acc[i][j][r] = 0.f;

    const int TILES = 38;              // ceil(602/16)
    const int cb = colBase + wn * 32;

    AStage st;
    uint32_t bC[16], bN[16];

    lda(st, Abase, rowBase, lm, kq, 0);
    ldb(bC, W, 0, cb, tig, gid);
    sta(As[0], st, lm, kq);
    __syncthreads();

    int buf = 0;
    for (int tile = 0; tile < TILES; tile++) {
        bool more = (tile + 1 < TILES);
        if (more) {
            int k0 = (tile + 1) * 16;
            lda(st, Abase, rowBase, lm, kq, k0);
            ldb(bN, W, k0, cb, tig, gid);
        }
        compute_tile(As[buf], bC, acc, wm, lane);
        if (more) {
            sta(As[buf ^ 1], st, lm, kq);
            __syncthreads();
            buf ^= 1;
            #pragma unroll
            for (int i = 0; i < 16; i++) bC[i] = bN[i];
        }
    }

    #pragma unroll
    for (int mt = 0; mt < 4; mt++) {
        int r0 = rowBase + wm * 64 + mt * 16 + gid;
        int r1 = r0 + 8;
        #pragma unroll
        for (int nt = 0; nt < 4; nt++) {
            int c = cb + nt * 8 + tig * 2;
            if (PHASE == 0) {
                float bb0 = __ldg(&b0[c]);
                float bb1 = __ldg(&b0[c + 1]);
                if (r0 < N_DST0)
                    *(float2*)&g_h[(size_t)r0 * F_HID + c] =
                        make_float2(acc[mt][nt][0] + bb0, acc[mt][nt][1] + bb1);
                if (r1 < N_DST0)
                    *(float2*)&g_h[(size_t)r1 * F_HID + c] =
                        make_float2(acc[mt][nt][2] + bb0, acc[mt][nt][3] + bb1);
            } else {
                if (r0 < N_DST0) {
                    float2 p = *(const float2*)&g_h[(size_t)r0 * F_HID + c];
                    *(float2*)&g_h[(size_t)r0 * F_HID + c] =
                        make_float2(fmaxf(p.x + acc[mt][nt][0], 0.f),
                                    fmaxf(p.y + acc[mt][nt][1], 0.f));
                }
                if (r1 < N_DST0) {
                    float2 p = *(const float2*)&g_h[(size_t)r1 * F_HID + c];
                    *(float2*)&g_h[(size_t)r1 * F_HID + c] =
                        make_float2(fmaxf(p.x + acc[mt][nt][2], 0.f),
                                    fmaxf(p.y + acc[mt][nt][3], 0.f));
                }
            }
        }
    }
}

// ---------------- layer-1 scatter: one warp per edge ---------------------------
__global__ void k_scatter1(const int* __restrict__ src,
                           const int* __restrict__ dst) {
    int gthread = blockIdx.x * blockDim.x + threadIdx.x;
    int warp = gthread >> 5;
    int lane = threadIdx.x & 31;
    if (warp >= N_E1) return;
    int s = src[warp];
    int d = dst[warp];
    const float2* hs = (const float2*)(g_h + (size_t)s * F_HID);
    float*        ag = g_agg1 + (size_t)d * F_HID;
    #pragma unroll
    for (int f = lane; f < F_HID / 2; f += 32) {
        float2 v = hs[f];
        atomicAdd(ag + 2*f,     v.x);
        atomicAdd(ag + 2*f + 1, v.y);
    }
    if (lane == 0) atomicAdd(&g_cnt1[d], 1.f);
}

// ---------------- output GEMM: one block per row (mean folded in) -------------
__global__ void __launch_bounds__(64)
k_out(const float* __restrict__ Ws1,
      const float* __restrict__ Wn1,
      const float* __restrict__ b1,
      float* __restrict__ out) {
    __shared__ float hs[F_HID];
    __shared__ float as[F_HID];
    int row = blockIdx.x;
    int t = threadIdx.x;
    float inv = 1.f / fmaxf(g_cnt1[row], 1.f);
    float4 hv = ((const float4*)(g_h    + (size_t)row * F_HID))[t];
    float4 av = ((const float4*)(g_agg1 + (size_t)row * F_HID))[t];
    av.x *= inv; av.y *= inv; av.z *= inv; av.w *= inv;
    ((float4*)hs)[t] = hv;
    ((float4*)as)[t] = av;
    __syncthreads();
    if (t < F_OUT) {
        float acc = __ldg(&b1[t]);
        #pragma unroll 8
        for (int k = 0; k < F_HID; k++) {
            acc += hs[k] * __ldg(&Ws1[k * F_OUT + t]);
            acc += as[k] * __ldg(&Wn1[k * F_OUT + t]);
        }
        out[row * F_OUT + t] = acc;
    }
}

// ---------------- launch ------------------------------------------------------
extern "C" void kernel_launch(void* const* d_in, const int* in_sizes, int n_in,
                              void* d_out, int out_size) {
    const float* x      = (const float*)d_in[0];
    const float* Wself0 = (const float*)d_in[1];
    const float* Wneigh0= (const float*)d_in[2];
    const float* b0     = (const float*)d_in[3];
    const float* Wself1 = (const float*)d_in[4];
    const float* Wneigh1= (const float*)d_in[5];
    const float* b1     = (const float*)d_in[6];
    const int*   e0_src = (const int*)d_in[7];
    const int*   e0_dst = (const int*)d_in[8];
    const int*   e1_src = (const int*)d_in[9];
    const int*   e1_dst = (const int*)d_in[10];
    float* out = (float*)d_out;

    // side stream + fork/join events (host objects only; no device allocation)
    cudaStream_t s1;
    cudaStreamCreateWithFlags(&s1, cudaStreamNonBlocking);
    cudaEvent_t e_fork, e_join;
    cudaEventCreateWithFlags(&e_fork, cudaEventDisableTiming);
    cudaEventCreateWithFlags(&e_join, cudaEventDisableTiming);

    dim3 ggrid(F_HID / 64, (N_DST0 + 127) / 128);   // (4, 86)

    // fork: phase-0 GEMM (x @ Wself0 + b0) on side stream — independent of agg
    cudaEventRecord(e_fork, 0);
    cudaStreamWaitEvent(s1, e_fork, 0);
    k_gemm<0><<<ggrid, 128, 0, s1>>>(x, Wself0, b0);
    cudaEventRecord(e_join, s1);

    // main stream: CSR build + pull aggregation (DRAM-bound; overlaps gemm<0>)
    k_zero<<<256, 256>>>();
    k_hist<<<(N_E0 + 255) / 256, 256>>>(e0_dst);
    k_prefix<<<1, 1024>>>();
    k_fill<<<(N_E0 + 255) / 256, 256>>>(e0_src, e0_dst);
    k_agg0<<<N_DST0, 256>>>(x);

    // join, then phase-1 GEMM (agg @ Wneigh0, add + relu)
    cudaStreamWaitEvent(0, e_join, 0);
    k_gemm<1><<<ggrid, 128>>>(nullptr, Wneigh0, b0);

    {
        int blocks = (N_E1 * 32 + 255) / 256;
        k_scatter1<<<blocks, 256>>>(e1_src, e1_dst);
    }
    k_out<<<N_DST1, 64>>>(Wself1, Wneigh1, b1, out);
}